// round 2
// baseline (speedup 1.0000x reference)
#include <cuda_runtime.h>
#include <cstdint>

// MeanAggregator: out[b, :] = (1/K) * sum_k embed[neigh_ids[b,k], :]
// B=8192, K=32, D=128, embed: [V=100000, 128] fp32.
// neigh_ids declared int64 in the reference, but JAX without x64 silently
// produces int32 — detect the actual width on device.

static constexpr int B = 8192;
static constexpr int K = 32;
static constexpr int D4 = 32;   // D/4
static constexpr long long V = 100000;

__device__ int g_ids_are_64 = 0;

// Decide whether the id buffer is int64 or int32.
// If int64: every value (B*K of them) lies in [0, V). If the buffer is really
// int32 data, interpreting pairs as int64 gives (hi<<32)|lo with hi a random
// id in [0,100000) -> out of range unless hi==0; checking 1024 consecutive
// pairs makes a false positive essentially impossible for random ids.
__global__ void detect_idx_width_kernel(const long long* __restrict__ ids_as64)
{
    if (blockIdx.x != 0 || threadIdx.x != 0) return;
    int ok64 = 1;
    for (int i = 0; i < 1024; ++i) {
        long long v = ids_as64[i];
        if (v < 0 || v >= V) { ok64 = 0; break; }
    }
    g_ids_are_64 = ok64;
}

__global__ __launch_bounds__(256) void mean_agg_kernel(
    const void* __restrict__ neigh_ids_raw,    // [B, K] int32 or int64
    const float4* __restrict__ embed,          // [V, D4]
    float4* __restrict__ out)                  // [B, D4]
{
    const int warp_global = (blockIdx.x * blockDim.x + threadIdx.x) >> 5;
    const int lane = threadIdx.x & 31;
    if (warp_global >= B) return;

    const int wide = g_ids_are_64;

    // Lane k holds the k-th neighbor id for this row.
    long long my_id;
    if (wide) {
        my_id = ((const long long*)neigh_ids_raw)[warp_global * K + lane];
    } else {
        my_id = (long long)((const int*)neigh_ids_raw)[warp_global * K + lane];
    }

    float4 acc = make_float4(0.f, 0.f, 0.f, 0.f);

#pragma unroll
    for (int k = 0; k < K; ++k) {
        long long nid = __shfl_sync(0xffffffffu, my_id, k);
        float4 v = __ldg(&embed[nid * D4 + lane]);
        acc.x += v.x;
        acc.y += v.y;
        acc.z += v.z;
        acc.w += v.w;
    }

    const float inv_k = 1.0f / (float)K;
    acc.x *= inv_k;
    acc.y *= inv_k;
    acc.z *= inv_k;
    acc.w *= inv_k;

    out[warp_global * D4 + lane] = acc;
}

extern "C" void kernel_launch(void* const* d_in, const int* in_sizes, int n_in,
                              void* d_out, int out_size)
{
    // Identify inputs by element count, not position.
    // neigh_ids: B*K = 262144 elements; embed: V*D = 12,800,000 elements.
    const void* neigh_ids = d_in[0];
    const void* embed = d_in[1];
    if (n_in >= 2) {
        if (in_sizes[0] == (int)(V * 128) || in_sizes[1] == B * K) {
            embed = d_in[0];
            neigh_ids = d_in[1];
        }
    }

    detect_idx_width_kernel<<<1, 32>>>((const long long*)neigh_ids);

    const int threads = 256;  // 8 warps/block
    const int blocks = B / (threads / 32);  // 1024
    mean_agg_kernel<<<blocks, threads>>>(neigh_ids, (const float4*)embed,
                                         (float4*)d_out);
}